// round 11
// baseline (speedup 1.0000x reference)
#include <cuda_runtime.h>
#include <cuda_fp16.h>
#include <math.h>
#include <stdint.h>

// ---------------------------------------------------------------- constants
#define NB     16
#define CC     512
#define HWP    6144            // 64*96
#define WW     96
#define PX_TILE 128            // pixels per CTA
#define TILES_PER_IMG 48       // 6144/128
#define NKT    32              // 32 k-tiles of 16 = K 512
#define NTILES 7               // 7 n-tiles of 8 = 56 cols (54 real)

// per-warp ring
#define STAGES 6
#define AHEAD  5
#define ROWF   20                              // floats per row (16 px + 4 pad)
#define STAGE_FLOATS (16 * ROWF)               // 320
#define STAGE_BYTES  (STAGE_FLOATS * 4)        // 1280
#define WRING_FLOATS (STAGES * STAGE_FLOATS)   // 1920
#define WRING_BYTES  (WRING_FLOATS * 4)        // 7680
#define SMEM_TOTAL   (8 * WRING_BYTES)         // 61440

// Output layout (floats): [rpn_loc | rpn_score | rpn_fg | anchor]
#define SC_BASE   3538944
#define FG_BASE   5308416
#define ANCH_BASE 6193152

// B fragments (fp16): [ktile(32)][lane(32)][16 u32 (7 ntiles*2 + pad)]
__device__ uint32_t g_bfrag[NKT * 32 * 16];   // 64 KB
__device__ float g_bias[64];

// ---------------------------------------------------------------- helpers
__device__ __forceinline__ uint32_t smem_u32(const void* p) {
    uint32_t a;
    asm("{ .reg .u64 t; cvta.to.shared.u64 t, %1; cvt.u32.u64 %0, t; }"
        : "=r"(a) : "l"(p));
    return a;
}

#define MMA16816(c, a, b0, b1)                                                \
    asm volatile("mma.sync.aligned.m16n8k16.row.col.f32.f16.f16.f32 "         \
        "{%0,%1,%2,%3}, {%4,%5,%6,%7}, {%8,%9}, {%0,%1,%2,%3};"               \
        : "+f"((c)[0]), "+f"((c)[1]), "+f"((c)[2]), "+f"((c)[3])              \
        : "r"((a)[0]), "r"((a)[1]), "r"((a)[2]), "r"((a)[3]),                 \
          "r"(b0), "r"(b1))

#define CVT2(d, flo, fhi)                                                     \
    asm("cvt.rn.f16x2.f32 %0, %1, %2;" : "=r"(d) : "f"(fhi), "f"(flo))

// per-warp stage issue: lane copies row (lane&15), chunks {l>>4, 2+(l>>4)}
// (two 16B cp.async = 32B of the 64B row), then commits one group.
#define ISSUE_W(DST, SRC)                                                     \
    asm volatile("cp.async.ca.shared.global [%0], [%1], 16;\n\t"              \
                 "cp.async.ca.shared.global [%2], [%3], 16;\n\t"              \
                 "cp.async.commit_group;"                                     \
        :: "r"(DST), "l"(SRC), "r"((DST) + 32), "l"((SRC) + 8) : "memory")

// ---------------------------------------------------------------- helper kernel
// Fused: B-fragment bake (fp16) + bias + anchors. 2 launches/call total.
__global__ void pack_w_kernel(const float* __restrict__ loc_w,
                              const float* __restrict__ loc_b,
                              const float* __restrict__ score_w,
                              const float* __restrict__ score_b,
                              float* __restrict__ out_anch) {
    int i = blockIdx.x * blockDim.x + threadIdx.x;

    // ---- B fragments: 32*32*8 = 8192 slots
    if (i < 8192) {
        int kt   = i >> 8;           // ktile 0..31
        int lane = (i >> 3) & 31;
        int nts  = i & 7;            // ntile slot (7 = zero pad)
        int o    = nts * 8 + (lane >> 2);
        int k0   = kt * 16 + 2 * (lane & 3);

        float w[4];
        #pragma unroll
        for (int q = 0; q < 4; q++) {
            int c = k0 + (q & 1) + (q >> 1) * 8;
            float v = 0.0f;
            if (o < 36)       v = loc_w[o * CC + c];
            else if (o < 54)  v = score_w[(o - 36) * CC + c];
            w[q] = v;
        }
        unsigned short u[4];
        #pragma unroll
        for (int q = 0; q < 4; q++)
            u[q] = __half_as_ushort(__float2half_rn(w[q]));
        int frag = kt * 32 + lane;
        g_bfrag[frag * 16 + nts * 2]     = (uint32_t)u[0] | ((uint32_t)u[1] << 16);
        g_bfrag[frag * 16 + nts * 2 + 1] = (uint32_t)u[2] | ((uint32_t)u[3] << 16);
    }

    // ---- bias
    if (i < 64) {
        float b = 0.0f;
        if (i < 36)       b = loc_b[i];
        else if (i < 54)  b = score_b[i - 36];
        g_bias[i] = b;
    }

    // ---- anchors
    if (i < HWP * 9) {
        int hw = i / 9, a = i % 9;
        int hy = hw / WW, wx = hw % WW;
        const double ratios[3] = {0.5, 1.0, 2.0};
        const double scales[3] = {8.0, 16.0, 32.0};
        double r = ratios[a / 3];
        double s = scales[a % 3];
        double ha = 16.0 * s * sqrt(r);
        double wa = 16.0 * s * sqrt(1.0 / r);
        float sy = (float)(hy * 16);
        float sx = (float)(wx * 16);
        float4 v;
        v.x = sy + (float)(8.0 - ha * 0.5);
        v.y = sx + (float)(8.0 - wa * 0.5);
        v.z = sy + (float)(8.0 + ha * 0.5);
        v.w = sx + (float)(8.0 + wa * 0.5);
        reinterpret_cast<float4*>(out_anch)[i] = v;
    }
}

// ---------------------------------------------------------------- main
// CTA = 128 px x 56 outs, 256 threads / 8 warps, warp -> 16 px (1 m-tile).
// FULLY DECOUPLED WARPS: each warp owns a private 6-stage cp.async ring for
// its 16-px slice (rows padded to 20 floats, conflict-free). No __syncthreads,
// no mbarriers: per-thread cp.async groups + __syncwarp only. 5 stages in
// flight per warp; warps drift freely and cover each other's stalls.
__global__ __launch_bounds__(256, 3)
void rpn_hmma_kernel(const float* __restrict__ x, float* __restrict__ out) {
    extern __shared__ __align__(16) float ringf[];

    const int tid  = threadIdx.x;
    const int lane = tid & 31;
    const int wid  = tid >> 5;
    const int b    = blockIdx.x;
    const int n    = b / TILES_PER_IMG;
    const int px0  = (b % TILES_PER_IMG) * PX_TILE;

    // producer per-lane mapping: row = lane&15 (channel), chunk = lane>>4
    const int prow = lane & 15;
    const int pchk = lane >> 4;
    const uint32_t wring_u = smem_u32(ringf) + wid * WRING_BYTES;
    const uint32_t pdst    = wring_u + (uint32_t)(prow * (ROWF * 4) + pchk * 16);
    // src floats: x[n, row, px0 + wid*16 + pchk*4 .. +4] (+32B pair in macro)
    const float* psrc = x + (size_t)n * CC * HWP + (size_t)prow * HWP
                        + px0 + wid * 16 + pchk * 4;

    // consumer: c0 = 2*(lane&3), p = lane>>2 within warp slice
    const float* cbase = ringf + wid * WRING_FLOATS
                         + (2 * (lane & 3)) * ROWF + (lane >> 2);

    float acc[NTILES][4];
    #pragma unroll
    for (int nt = 0; nt < NTILES; nt++)
        #pragma unroll
        for (int q = 0; q < 4; q++) acc[nt][q] = 0.0f;

    // prologue: stages 0..AHEAD-1
    #pragma unroll
    for (int s = 0; s < AHEAD; s++)
        ISSUE_W(pdst + s * STAGE_BYTES, psrc + (size_t)(s * 16) * HWP);

    const uint4* bp = reinterpret_cast<const uint4*>(g_bfrag + (size_t)lane * 16);
    int cslot = 0;          // slot of stage kt
    int wslot = AHEAD;      // slot for stage kt+AHEAD

    for (int kt = 0; kt < NKT; kt++) {
        // issue stage kt+AHEAD (its slot was consumed at kt-1) or empty group
        if (kt + AHEAD < NKT) {
            ISSUE_W(pdst + wslot * STAGE_BYTES,
                    psrc + (size_t)((kt + AHEAD) * 16) * HWP);
        } else {
            asm volatile("cp.async.commit_group;" ::: "memory");
        }
        if (++wslot == STAGES) wslot = 0;

        // stage kt is the (AHEAD+1)-th newest group -> wait_group AHEAD
        asm volatile("cp.async.wait_group %0;" :: "n"(AHEAD) : "memory");
        __syncwarp();

        // consume stage kt
        const float* c = cbase + cslot * STAGE_FLOATS;
        float f0 = c[0],            f1 = c[8];             // ch c0
        float f2 = c[ROWF],         f3 = c[ROWF + 8];      // ch c0+1
        float f4 = c[8 * ROWF],     f5 = c[8 * ROWF + 8];  // ch c0+8
        float f6 = c[9 * ROWF],     f7 = c[9 * ROWF + 8];  // ch c0+9
        uint32_t a[4];
        CVT2(a[0], f0, f2);
        CVT2(a[1], f1, f3);
        CVT2(a[2], f4, f6);
        CVT2(a[3], f5, f7);

        uint4 q0 = bp[0], q1 = bp[1], q2 = bp[2], q3 = bp[3];
        MMA16816(acc[0], a, q0.x, q0.y);
        MMA16816(acc[1], a, q0.z, q0.w);
        MMA16816(acc[2], a, q1.x, q1.y);
        MMA16816(acc[3], a, q1.z, q1.w);
        MMA16816(acc[4], a, q2.x, q2.y);
        MMA16816(acc[5], a, q2.z, q2.w);
        MMA16816(acc[6], a, q3.x, q3.y);

        bp += 128;   // next ktile block: 32 lanes x 16 u32 = 128 uint4
        if (++cslot == STAGES) cslot = 0;
    }

    // ---- epilogue straight from fragments
    const int l4 = lane >> 2;
    const int l2 = (lane & 3) * 2;
    float bias0[NTILES], bias1[NTILES];
    #pragma unroll
    for (int nt = 0; nt < NTILES; nt++) {
        bias0[nt] = g_bias[nt * 8 + l2];
        bias1[nt] = g_bias[nt * 8 + l2 + 1];
    }

    #pragma unroll
    for (int h = 0; h < 2; h++) {
        int pix = wid * 16 + h * 8 + l4;
        size_t gpix = (size_t)n * HWP + px0 + pix;
        float* lb = out + gpix * 36;
        float* sb = out + SC_BASE + gpix * 18;
        float* fb = out + FG_BASE + gpix * 9;
        #pragma unroll
        for (int nt = 0; nt < NTILES; nt++) {
            int col = nt * 8 + l2;
            float v0 = acc[nt][2 * h]     + bias0[nt];
            float v1 = acc[nt][2 * h + 1] + bias1[nt];
            if (col < 36) {
                *reinterpret_cast<float2*>(lb + col) = make_float2(v0, v1);
            } else if (col < 54) {
                *reinterpret_cast<float2*>(sb + (col - 36)) = make_float2(v0, v1);
                fb[(col - 36) >> 1] = 1.0f / (1.0f + __expf(v0 - v1));
            }
        }
    }
}

// ---------------------------------------------------------------- launch
extern "C" void kernel_launch(void* const* d_in, const int* in_sizes, int n_in,
                              void* d_out, int out_size) {
    (void)in_sizes; (void)n_in; (void)out_size;
    const float* x       = (const float*)d_in[0];
    const float* loc_w   = (const float*)d_in[1];
    const float* loc_b   = (const float*)d_in[2];
    const float* score_w = (const float*)d_in[3];
    const float* score_b = (const float*)d_in[4];
    float* out = (float*)d_out;

    // opt-in to >48KB dynamic smem (host attribute, capture-safe)
    static int smem_set = 0;
    if (!smem_set) {
        cudaFuncSetAttribute(rpn_hmma_kernel,
                             cudaFuncAttributeMaxDynamicSharedMemorySize,
                             SMEM_TOTAL);
        smem_set = 1;
    }

    pack_w_kernel<<<(HWP * 9 + 255) / 256, 256>>>(
        loc_w, loc_b, score_w, score_b, out + ANCH_BASE);

    rpn_hmma_kernel<<<NB * TILES_PER_IMG, 256, SMEM_TOTAL>>>(x, out);
}

// round 12
// speedup vs baseline: 1.0819x; 1.0819x over previous
#include <cuda_runtime.h>
#include <cuda_fp16.h>
#include <math.h>
#include <stdint.h>

// ---------------------------------------------------------------- constants
#define NB     16
#define CC     512
#define HWP    6144            // 64*96
#define WW     96
#define PX_TILE 256            // pixels per CTA (1KB-contiguous channel rows)
#define TILES_PER_IMG 24       // 6144/256
#define NKT    32              // 32 k-tiles of 16 = K 512
#define NTILES 7               // 7 n-tiles of 8 = 56 cols (54 real)
#define STAGES 4
#define AHEAD  3               // stages in flight
#define ROWW   260             // floats per smem row (256 px + 4 pad)
#define STAGE_FLOATS (16 * ROWW)            // 4160
#define STAGE_BYTES  (STAGE_FLOATS * 4)     // 16640
#define SMEM_TOTAL   (STAGES * STAGE_BYTES) // 66560

// Output layout (floats): [rpn_loc | rpn_score | rpn_fg | anchor]
#define SC_BASE   3538944
#define FG_BASE   5308416
#define ANCH_BASE 6193152

// B fragments (fp16): [ktile(32)][lane(32)][16 u32 (7 ntiles*2 + pad)]
__device__ uint32_t g_bfrag[NKT * 32 * 16];   // 64 KB
__device__ float g_bias[64];

// ---------------------------------------------------------------- helpers
__device__ __forceinline__ uint32_t smem_u32(const void* p) {
    uint32_t a;
    asm("{ .reg .u64 t; cvta.to.shared.u64 t, %1; cvt.u32.u64 %0, t; }"
        : "=r"(a) : "l"(p));
    return a;
}

#define MMA16816(c, a, b0, b1)                                                \
    asm volatile("mma.sync.aligned.m16n8k16.row.col.f32.f16.f16.f32 "         \
        "{%0,%1,%2,%3}, {%4,%5,%6,%7}, {%8,%9}, {%0,%1,%2,%3};"               \
        : "+f"((c)[0]), "+f"((c)[1]), "+f"((c)[2]), "+f"((c)[3])              \
        : "r"((a)[0]), "r"((a)[1]), "r"((a)[2]), "r"((a)[3]),                 \
          "r"(b0), "r"(b1))

#define CVT2(d, flo, fhi)                                                     \
    asm("cvt.rn.f16x2.f32 %0, %1, %2;" : "=r"(d) : "f"(fhi), "f"(flo))

// stage issue: thread copies row (t>>5), 32B at (t&31)*32 (two 16B cp.async)
#define ISSUE_P(SRC, DST)                                                     \
    asm volatile("cp.async.ca.shared.global [%0], [%1], 16;\n\t"              \
                 "cp.async.ca.shared.global [%2], [%3], 16;\n\t"              \
                 "cp.async.commit_group;"                                     \
        :: "r"(DST), "l"(SRC), "r"((DST) + 16), "l"((SRC) + 4) : "memory")

// ---------------------------------------------------------------- helper kernel
// Fused: B-fragment bake (fp16) + bias + anchors. 2 launches/call total.
__global__ void pack_w_kernel(const float* __restrict__ loc_w,
                              const float* __restrict__ loc_b,
                              const float* __restrict__ score_w,
                              const float* __restrict__ score_b,
                              float* __restrict__ out_anch) {
    int i = blockIdx.x * blockDim.x + threadIdx.x;

    // ---- B fragments: 32*32*8 = 8192 slots
    if (i < 8192) {
        int kt   = i >> 8;           // ktile 0..31
        int lane = (i >> 3) & 31;
        int nts  = i & 7;            // ntile slot (7 = zero pad)
        int o    = nts * 8 + (lane >> 2);
        int k0   = kt * 16 + 2 * (lane & 3);

        float w[4];
        #pragma unroll
        for (int q = 0; q < 4; q++) {
            int c = k0 + (q & 1) + (q >> 1) * 8;
            float v = 0.0f;
            if (o < 36)       v = loc_w[o * CC + c];
            else if (o < 54)  v = score_w[(o - 36) * CC + c];
            w[q] = v;
        }
        unsigned short u[4];
        #pragma unroll
        for (int q = 0; q < 4; q++)
            u[q] = __half_as_ushort(__float2half_rn(w[q]));
        int frag = kt * 32 + lane;
        g_bfrag[frag * 16 + nts * 2]     = (uint32_t)u[0] | ((uint32_t)u[1] << 16);
        g_bfrag[frag * 16 + nts * 2 + 1] = (uint32_t)u[2] | ((uint32_t)u[3] << 16);
    }

    // ---- bias
    if (i < 64) {
        float b = 0.0f;
        if (i < 36)       b = loc_b[i];
        else if (i < 54)  b = score_b[i - 36];
        g_bias[i] = b;
    }

    // ---- anchors
    if (i < HWP * 9) {
        int hw = i / 9, a = i % 9;
        int hy = hw / WW, wx = hw % WW;
        const double ratios[3] = {0.5, 1.0, 2.0};
        const double scales[3] = {8.0, 16.0, 32.0};
        double r = ratios[a / 3];
        double s = scales[a % 3];
        double ha = 16.0 * s * sqrt(r);
        double wa = 16.0 * s * sqrt(1.0 / r);
        float sy = (float)(hy * 16);
        float sx = (float)(wx * 16);
        float4 v;
        v.x = sy + (float)(8.0 - ha * 0.5);
        v.y = sx + (float)(8.0 - wa * 0.5);
        v.z = sy + (float)(8.0 + ha * 0.5);
        v.w = sx + (float)(8.0 + wa * 0.5);
        reinterpret_cast<float4*>(out_anch)[i] = v;
    }
}

// ---------------------------------------------------------------- main
// CTA = 256 px x 56 outs, 512 threads / 16 warps, warp -> 16 px (1 m-tile).
// cp.async 4-stage ring of 16ch x 256px fp32 stages (1KB-contiguous rows),
// 3 stages in flight, wait_group+barrier per ktile (R9 discipline).
// Consumer: 8 conflict-free LDS.32 -> cvt fp16 -> 7 HMMA per ktile per warp.
__global__ __launch_bounds__(512, 2)
void rpn_hmma_kernel(const float* __restrict__ x, float* __restrict__ out) {
    extern __shared__ __align__(16) float ringf[];

    const int tid  = threadIdx.x;
    const int lane = tid & 31;
    const int wid  = tid >> 5;
    const int b    = blockIdx.x;
    const int n    = b / TILES_PER_IMG;
    const int px0  = (b % TILES_PER_IMG) * PX_TILE;

    const float* xn = x + (size_t)n * CC * HWP + px0;

    // producer: thread copies row (tid>>5), 32B at (tid&31)*32
    const int prow = tid >> 5;          // 0..15 (channel within ktile)
    const int pcol = (tid & 31) * 8;    // float offset within row
    const uint32_t ring_u = smem_u32(ringf);
    const uint32_t pdst   = ring_u + (uint32_t)(prow * ROWW + pcol) * 4;
    const float*   psrc   = xn + (size_t)prow * HWP + pcol;

    // consumer: lane reads ch = 2*(lane&3)+{0,1,8,9}, px = wid*16+(lane>>2)+{0,8}
    const float* cbase = ringf + (2 * (lane & 3)) * ROWW + wid * 16 + (lane >> 2);

    float acc[NTILES][4];
    #pragma unroll
    for (int nt = 0; nt < NTILES; nt++)
        #pragma unroll
        for (int q = 0; q < 4; q++) acc[nt][q] = 0.0f;

    // prologue: stages 0..2
    ISSUE_P(psrc,                    pdst);
    ISSUE_P(psrc + (size_t)16 * HWP, pdst + STAGE_BYTES);
    ISSUE_P(psrc + (size_t)32 * HWP, pdst + 2 * STAGE_BYTES);

    const uint4* bp = reinterpret_cast<const uint4*>(g_bfrag + (size_t)lane * 16);
    const float* wsrc = psrc + (size_t)48 * HWP;   // stage kt+3 source
    uint32_t soff_w = 3 * STAGE_BYTES;             // slot (kt+3)%4
    int soff_c = 0;                                // slot kt%4

    for (int kt = 0; kt < NKT; kt++) {
        // outstanding groups kt..kt+2 -> wait_group 2 drains stage kt
        asm volatile("cp.async.wait_group 2;" ::: "memory");
        __syncthreads();

        // issue stage kt+3 into slot of kt-1 (all reads retired at barrier)
        if (kt + 3 < NKT) {
            ISSUE_P(wsrc, pdst + soff_w);
            wsrc += (size_t)16 * HWP;
            soff_w += STAGE_BYTES;
            if (soff_w == STAGES * STAGE_BYTES) soff_w = 0;
        } else {
            asm volatile("cp.async.commit_group;" ::: "memory");
        }

        // consume stage kt
        const float* c = cbase + soff_c;
        float f0 = c[0],          f1 = c[8];            // ch c0
        float f2 = c[ROWW],       f3 = c[ROWW + 8];     // ch c0+1
        float f4 = c[8 * ROWW],   f5 = c[8 * ROWW + 8]; // ch c0+8
        float f6 = c[9 * ROWW],   f7 = c[9 * ROWW + 8]; // ch c0+9
        uint32_t a[4];
        CVT2(a[0], f0, f2);
        CVT2(a[1], f1, f3);
        CVT2(a[2], f4, f6);
        CVT2(a[3], f5, f7);

        uint4 q0 = bp[0], q1 = bp[1], q2 = bp[2], q3 = bp[3];
        MMA16816(acc[0], a, q0.x, q0.y);
        MMA16816(acc[1], a, q0.z, q0.w);
        MMA16816(acc[2], a, q1.x, q1.y);
        MMA16816(acc[3], a, q1.z, q1.w);
        MMA16816(acc[4], a, q2.x, q2.y);
        MMA16816(acc[5], a, q2.z, q2.w);
        MMA16816(acc[6], a, q3.x, q3.y);

        bp += 128;   // next ktile block: 32 lanes x 16 u32 = 128 uint4
        soff_c += STAGE_FLOATS;
        if (soff_c == STAGES * STAGE_FLOATS) soff_c = 0;
    }

    // ---- epilogue straight from fragments
    const int l4 = lane >> 2;
    const int l2 = (lane & 3) * 2;
    float bias0[NTILES], bias1[NTILES];
    #pragma unroll
    for (int nt = 0; nt < NTILES; nt++) {
        bias0[nt] = g_bias[nt * 8 + l2];
        bias1[nt] = g_bias[nt * 8 + l2 + 1];
    }

    #pragma unroll
    for (int h = 0; h < 2; h++) {
        int pix = wid * 16 + h * 8 + l4;
        size_t gpix = (size_t)n * HWP + px0 + pix;
        float* lb = out + gpix * 36;
        float* sb = out + SC_BASE + gpix * 18;
        float* fb = out + FG_BASE + gpix * 9;
        #pragma unroll
        for (int nt = 0; nt < NTILES; nt++) {
            int col = nt * 8 + l2;
            float v0 = acc[nt][2 * h]     + bias0[nt];
            float v1 = acc[nt][2 * h + 1] + bias1[nt];
            if (col < 36) {
                *reinterpret_cast<float2*>(lb + col) = make_float2(v0, v1);
            } else if (col < 54) {
                *reinterpret_cast<float2*>(sb + (col - 36)) = make_float2(v0, v1);
                fb[(col - 36) >> 1] = 1.0f / (1.0f + __expf(v0 - v1));
            }
        }
    }
}

// ---------------------------------------------------------------- launch
extern "C" void kernel_launch(void* const* d_in, const int* in_sizes, int n_in,
                              void* d_out, int out_size) {
    (void)in_sizes; (void)n_in; (void)out_size;
    const float* x       = (const float*)d_in[0];
    const float* loc_w   = (const float*)d_in[1];
    const float* loc_b   = (const float*)d_in[2];
    const float* score_w = (const float*)d_in[3];
    const float* score_b = (const float*)d_in[4];
    float* out = (float*)d_out;

    // opt-in to >48KB dynamic smem (host attribute, capture-safe)
    static int smem_set = 0;
    if (!smem_set) {
        cudaFuncSetAttribute(rpn_hmma_kernel,
                             cudaFuncAttributeMaxDynamicSharedMemorySize,
                             SMEM_TOTAL);
        smem_set = 1;
    }

    pack_w_kernel<<<(HWP * 9 + 255) / 256, 256>>>(
        loc_w, loc_b, score_w, score_b, out + ANCH_BASE);

    rpn_hmma_kernel<<<NB * TILES_PER_IMG, 512, SMEM_TOTAL>>>(x, out);
}

// round 13
// speedup vs baseline: 1.2664x; 1.1705x over previous
#include <cuda_runtime.h>
#include <cuda_fp16.h>
#include <math.h>
#include <stdint.h>

// ---------------------------------------------------------------- constants
#define NB     16
#define CC     512
#define HWP    6144            // 64*96
#define WW     96
#define PX_TILE 64             // pixels per CTA (small CTA -> many streams)
#define TILES_PER_IMG 96       // 6144/64
#define NKT    32              // 32 k-tiles of 16 = K 512
#define NTILES 7               // 7 n-tiles of 8 = 56 cols (54 real)
#define STAGES 5
#define ROWW   68              // floats per smem row (64 px + 4 pad)
#define STAGE_FLOATS (16 * ROWW)            // 1088
#define STAGE_BYTES  (STAGE_FLOATS * 4)     // 4352
#define SMEM_TOTAL   (STAGES * STAGE_BYTES) // 21760

// Output layout (floats): [rpn_loc | rpn_score | rpn_fg | anchor]
#define SC_BASE   3538944
#define FG_BASE   5308416
#define ANCH_BASE 6193152

// B fragments (fp16): [ktile(32)][lane(32)][16 u32 (7 ntiles*2 + pad)]
__device__ uint32_t g_bfrag[NKT * 32 * 16];   // 64 KB
__device__ float g_bias[64];

// ---------------------------------------------------------------- helpers
__device__ __forceinline__ uint32_t smem_u32(const void* p) {
    uint32_t a;
    asm("{ .reg .u64 t; cvta.to.shared.u64 t, %1; cvt.u32.u64 %0, t; }"
        : "=r"(a) : "l"(p));
    return a;
}

#define MMA16816(c, a, b0, b1)                                                \
    asm volatile("mma.sync.aligned.m16n8k16.row.col.f32.f16.f16.f32 "         \
        "{%0,%1,%2,%3}, {%4,%5,%6,%7}, {%8,%9}, {%0,%1,%2,%3};"               \
        : "+f"((c)[0]), "+f"((c)[1]), "+f"((c)[2]), "+f"((c)[3])              \
        : "r"((a)[0]), "r"((a)[1]), "r"((a)[2]), "r"((a)[3]),                 \
          "r"(b0), "r"(b1))

#define CVT2(d, flo, fhi)                                                     \
    asm("cvt.rn.f16x2.f32 %0, %1, %2;" : "=r"(d) : "f"(fhi), "f"(flo))

// stage issue: thread t copies row t>>3 (channel), 32B at (t&7)*32
#define ISSUE_P(SRC, DST)                                                     \
    asm volatile("cp.async.ca.shared.global [%0], [%1], 16;\n\t"              \
                 "cp.async.ca.shared.global [%2], [%3], 16;\n\t"              \
                 "cp.async.commit_group;"                                     \
        :: "r"(DST), "l"(SRC), "r"((DST) + 16), "l"((SRC) + 4) : "memory")

// ---------------------------------------------------------------- helper kernel
// Fused: B-fragment bake (fp16) + bias + anchors. 2 launches/call total.
__global__ void pack_w_kernel(const float* __restrict__ loc_w,
                              const float* __restrict__ loc_b,
                              const float* __restrict__ score_w,
                              const float* __restrict__ score_b,
                              float* __restrict__ out_anch) {
    int i = blockIdx.x * blockDim.x + threadIdx.x;

    // ---- B fragments: 32*32*8 = 8192 slots
    if (i < 8192) {
        int kt   = i >> 8;           // ktile 0..31
        int lane = (i >> 3) & 31;
        int nts  = i & 7;            // ntile slot (7 = zero pad)
        int o    = nts * 8 + (lane >> 2);
        int k0   = kt * 16 + 2 * (lane & 3);

        float w[4];
        #pragma unroll
        for (int q = 0; q < 4; q++) {
            int c = k0 + (q & 1) + (q >> 1) * 8;
            float v = 0.0f;
            if (o < 36)       v = loc_w[o * CC + c];
            else if (o < 54)  v = score_w[(o - 36) * CC + c];
            w[q] = v;
        }
        unsigned short u[4];
        #pragma unroll
        for (int q = 0; q < 4; q++)
            u[q] = __half_as_ushort(__float2half_rn(w[q]));
        int frag = kt * 32 + lane;
        g_bfrag[frag * 16 + nts * 2]     = (uint32_t)u[0] | ((uint32_t)u[1] << 16);
        g_bfrag[frag * 16 + nts * 2 + 1] = (uint32_t)u[2] | ((uint32_t)u[3] << 16);
    }

    // ---- bias
    if (i < 64) {
        float b = 0.0f;
        if (i < 36)       b = loc_b[i];
        else if (i < 54)  b = score_b[i - 36];
        g_bias[i] = b;
    }

    // ---- anchors
    if (i < HWP * 9) {
        int hw = i / 9, a = i % 9;
        int hy = hw / WW, wx = hw % WW;
        const double ratios[3] = {0.5, 1.0, 2.0};
        const double scales[3] = {8.0, 16.0, 32.0};
        double r = ratios[a / 3];
        double s = scales[a % 3];
        double ha = 16.0 * s * sqrt(r);
        double wa = 16.0 * s * sqrt(1.0 / r);
        float sy = (float)(hy * 16);
        float sx = (float)(wx * 16);
        float4 v;
        v.x = sy + (float)(8.0 - ha * 0.5);
        v.y = sx + (float)(8.0 - wa * 0.5);
        v.z = sy + (float)(8.0 + ha * 0.5);
        v.w = sx + (float)(8.0 + wa * 0.5);
        reinterpret_cast<float4*>(out_anch)[i] = v;
    }
}

// ---------------------------------------------------------------- main
// CTA = 64 px x 56 outs, 128 threads / 4 warps, warp -> 16 px (1 m-tile).
// Small CTAs maximize resident streams: 8 CTAs/SM (<=64 regs, 21.8KB smem)
// -> ~1184 concurrent DRAM streams. Pipeline/consumer identical to R9:
// cp.async 5-stage ring, 4 in flight, 8 conflict-free LDS -> cvt -> 7 HMMA.
__global__ __launch_bounds__(128, 8)
void rpn_hmma_kernel(const float* __restrict__ x, float* __restrict__ out) {
    extern __shared__ __align__(16) float ringf[];

    const int tid  = threadIdx.x;
    const int lane = tid & 31;
    const int wid  = tid >> 5;
    const int b    = blockIdx.x;
    const int n    = b / TILES_PER_IMG;
    const int px0  = (b % TILES_PER_IMG) * PX_TILE;

    const float* xn = x + (size_t)n * CC * HWP + px0;

    // producer: thread copies row (tid>>3), 32B at (tid&7)*32
    const int prow = tid >> 3;          // 0..15 (channel within ktile)
    const int pcol = (tid & 7) * 8;     // float offset within row (0..56)
    const uint32_t ring_u = smem_u32(ringf);
    const uint32_t pdst   = ring_u + (uint32_t)(prow * ROWW + pcol) * 4;
    const float*   psrc   = xn + (size_t)prow * HWP + pcol;

    // consumer: lane reads ch = 2*(lane&3)+{0,1,8,9}, px = wid*16+(lane>>2)+{0,8}
    const float* cbase = ringf + (2 * (lane & 3)) * ROWW + wid * 16 + (lane >> 2);

    float acc[NTILES][4];
    #pragma unroll
    for (int nt = 0; nt < NTILES; nt++)
        #pragma unroll
        for (int q = 0; q < 4; q++) acc[nt][q] = 0.0f;

    // prologue: stages 0..3
    ISSUE_P(psrc,                    pdst);
    ISSUE_P(psrc + (size_t)16 * HWP, pdst + STAGE_BYTES);
    ISSUE_P(psrc + (size_t)32 * HWP, pdst + 2 * STAGE_BYTES);
    ISSUE_P(psrc + (size_t)48 * HWP, pdst + 3 * STAGE_BYTES);

    const uint4* bp = reinterpret_cast<const uint4*>(g_bfrag + (size_t)lane * 16);
    const float* wsrc = psrc + (size_t)64 * HWP;   // stage kt+4 source
    uint32_t soff_w = 4 * STAGE_BYTES;             // slot (kt+4)%5
    int soff_c = 0;                                // slot kt%5

    for (int kt = 0; kt < NKT; kt++) {
        // outstanding groups kt..kt+3 -> wait_group 3 drains stage kt
        asm volatile("cp.async.wait_group 3;" ::: "memory");
        __syncthreads();

        // issue stage kt+4 into slot of kt-1 (reads retired at barrier)
        if (kt + 4 < NKT) {
            ISSUE_P(wsrc, pdst + soff_w);
            wsrc += (size_t)16 * HWP;
            soff_w += STAGE_BYTES;
            if (soff_w == STAGES * STAGE_BYTES) soff_w = 0;
        } else {
            asm volatile("cp.async.commit_group;" ::: "memory");
        }

        // consume stage kt
        const float* c = cbase + soff_c;
        float f0 = c[0],          f1 = c[8];            // ch c0
        float f2 = c[ROWW],       f3 = c[ROWW + 8];     // ch c0+1
        float f4 = c[8 * ROWW],   f5 = c[8 * ROWW + 8]; // ch c0+8
        float f6 = c[9 * ROWW],   f7 = c[9 * ROWW + 8]; // ch c0+9
        uint32_t a[4];
        CVT2(a[0], f0, f2);
        CVT2(a[1], f1, f3);
        CVT2(a[2], f4, f6);
        CVT2(a[3], f5, f7);

        uint4 q0 = bp[0], q1 = bp[1], q2 = bp[2], q3 = bp[3];
        MMA16816(acc[0], a, q0.x, q0.y);
        MMA16816(acc[1], a, q0.z, q0.w);
        MMA16816(acc[2], a, q1.x, q1.y);
        MMA16816(acc[3], a, q1.z, q1.w);
        MMA16816(acc[4], a, q2.x, q2.y);
        MMA16816(acc[5], a, q2.z, q2.w);
        MMA16816(acc[6], a, q3.x, q3.y);

        bp += 128;   // next ktile block: 32 lanes x 16 u32 = 128 uint4
        soff_c += STAGE_FLOATS;
        if (soff_c == STAGES * STAGE_FLOATS) soff_c = 0;
    }

    // ---- epilogue straight from fragments
    const int l4 = lane >> 2;
    const int l2 = (lane & 3) * 2;
    float bias0[NTILES], bias1[NTILES];
    #pragma unroll
    for (int nt = 0; nt < NTILES; nt++) {
        bias0[nt] = g_bias[nt * 8 + l2];
        bias1[nt] = g_bias[nt * 8 + l2 + 1];
    }

    #pragma unroll
    for (int h = 0; h < 2; h++) {
        int pix = wid * 16 + h * 8 + l4;
        size_t gpix = (size_t)n * HWP + px0 + pix;
        float* lb = out + gpix * 36;
        float* sb = out + SC_BASE + gpix * 18;
        float* fb = out + FG_BASE + gpix * 9;
        #pragma unroll
        for (int nt = 0; nt < NTILES; nt++) {
            int col = nt * 8 + l2;
            float v0 = acc[nt][2 * h]     + bias0[nt];
            float v1 = acc[nt][2 * h + 1] + bias1[nt];
            if (col < 36) {
                *reinterpret_cast<float2*>(lb + col) = make_float2(v0, v1);
            } else if (col < 54) {
                *reinterpret_cast<float2*>(sb + (col - 36)) = make_float2(v0, v1);
                fb[(col - 36) >> 1] = 1.0f / (1.0f + __expf(v0 - v1));
            }
        }
    }
}

// ---------------------------------------------------------------- launch
extern "C" void kernel_launch(void* const* d_in, const int* in_sizes, int n_in,
                              void* d_out, int out_size) {
    (void)in_sizes; (void)n_in; (void)out_size;
    const float* x       = (const float*)d_in[0];
    const float* loc_w   = (const float*)d_in[1];
    const float* loc_b   = (const float*)d_in[2];
    const float* score_w = (const float*)d_in[3];
    const float* score_b = (const float*)d_in[4];
    float* out = (float*)d_out;

    // opt-in to dynamic smem sizing (host attribute, capture-safe)
    static int smem_set = 0;
    if (!smem_set) {
        cudaFuncSetAttribute(rpn_hmma_kernel,
                             cudaFuncAttributeMaxDynamicSharedMemorySize,
                             SMEM_TOTAL);
        smem_set = 1;
    }

    pack_w_kernel<<<(HWP * 9 + 255) / 256, 256>>>(
        loc_w, loc_b, score_w, score_b, out + ANCH_BASE);

    rpn_hmma_kernel<<<NB * TILES_PER_IMG, 128, SMEM_TOTAL>>>(x, out);
}

// round 15
// speedup vs baseline: 1.2884x; 1.0174x over previous
#include <cuda_runtime.h>
#include <cuda_fp16.h>
#include <math.h>
#include <stdint.h>

// ---------------------------------------------------------------- constants
#define NB     16
#define CC     512
#define HWP    6144            // 64*96
#define WW     96
#define PX_TILE 256            // pixels per CTA
#define TILES_PER_IMG 24       // 6144/256
#define NKT    32              // 32 k-tiles of 16 = K 512
#define NTILES 7               // 7 n-tiles of 8 = 56 cols (54 real)
#define STAGES 4
#define ROWW   260             // floats per smem row (256 px + 4 pad)
#define STAGE_FLOATS (16 * ROWW)            // 4160
#define STAGE_BYTES  (STAGE_FLOATS * 4)     // 16640
#define SMEM_TOTAL   (STAGES * STAGE_BYTES) // 66560 (>= 64512 epi staging)

// epilogue staging offsets (floats, within ring SMEM)
#define EPI_LOC   0                         // 256*36 = 9216
#define EPI_SC    9216                      // 256*18 = 4608
#define EPI_FG    13824                     // 256*9  = 2304 -> 16128 total

// Output layout (floats): [rpn_loc | rpn_score | rpn_fg | anchor]
#define SC_BASE   3538944
#define FG_BASE   5308416
#define ANCH_BASE 6193152

// B fragments (fp16): [ktile(32)][lane(32)][16 u32 (7 ntiles*2 + pad)]
__device__ uint32_t g_bfrag[NKT * 32 * 16];   // 64 KB
__device__ float g_bias[64];

// ---------------------------------------------------------------- helpers
__device__ __forceinline__ uint32_t smem_u32(const void* p) {
    uint32_t a;
    asm("{ .reg .u64 t; cvta.to.shared.u64 t, %1; cvt.u32.u64 %0, t; }"
        : "=r"(a) : "l"(p));
    return a;
}

#define MMA16816(c, a, b0, b1)                                                \
    asm volatile("mma.sync.aligned.m16n8k16.row.col.f32.f16.f16.f32 "         \
        "{%0,%1,%2,%3}, {%4,%5,%6,%7}, {%8,%9}, {%0,%1,%2,%3};"               \
        : "+f"((c)[0]), "+f"((c)[1]), "+f"((c)[2]), "+f"((c)[3])              \
        : "r"((a)[0]), "r"((a)[1]), "r"((a)[2]), "r"((a)[3]),                 \
          "r"(b0), "r"(b1))

#define CVT2(d, flo, fhi)                                                     \
    asm("cvt.rn.f16x2.f32 %0, %1, %2;" : "=r"(d) : "f"(fhi), "f"(flo))

// stage issue: thread copies row (t>>4), 64B at (t&15)*64 (4x 16B cp.async)
#define ISSUE_P(SRC, DST)                                                     \
    asm volatile("cp.async.ca.shared.global [%0], [%1], 16;\n\t"              \
                 "cp.async.ca.shared.global [%2], [%3], 16;\n\t"              \
                 "cp.async.ca.shared.global [%4], [%5], 16;\n\t"              \
                 "cp.async.ca.shared.global [%6], [%7], 16;\n\t"              \
                 "cp.async.commit_group;"                                     \
        :: "r"(DST),      "l"(SRC),      "r"((DST)+16), "l"((SRC)+4),         \
           "r"((DST)+32), "l"((SRC)+8),  "r"((DST)+48), "l"((SRC)+12)         \
        : "memory")

// ---------------------------------------------------------------- helper kernel
// Fused: B-fragment bake (fp16) + bias + anchors. 2 launches/call total.
__global__ void pack_w_kernel(const float* __restrict__ loc_w,
                              const float* __restrict__ loc_b,
                              const float* __restrict__ score_w,
                              const float* __restrict__ score_b,
                              float* __restrict__ out_anch) {
    int i = blockIdx.x * blockDim.x + threadIdx.x;

    // ---- B fragments: 32*32*8 = 8192 slots
    if (i < 8192) {
        int kt   = i >> 8;           // ktile 0..31
        int lane = (i >> 3) & 31;
        int nts  = i & 7;            // ntile slot (7 = zero pad)
        int o    = nts * 8 + (lane >> 2);
        int k0   = kt * 16 + 2 * (lane & 3);

        float w[4];
        #pragma unroll
        for (int q = 0; q < 4; q++) {
            int c = k0 + (q & 1) + (q >> 1) * 8;
            float v = 0.0f;
            if (o < 36)       v = loc_w[o * CC + c];
            else if (o < 54)  v = score_w[(o - 36) * CC + c];
            w[q] = v;
        }
        unsigned short u[4];
        #pragma unroll
        for (int q = 0; q < 4; q++)
            u[q] = __half_as_ushort(__float2half_rn(w[q]));
        int frag = kt * 32 + lane;
        g_bfrag[frag * 16 + nts * 2]     = (uint32_t)u[0] | ((uint32_t)u[1] << 16);
        g_bfrag[frag * 16 + nts * 2 + 1] = (uint32_t)u[2] | ((uint32_t)u[3] << 16);
    }

    // ---- bias
    if (i < 64) {
        float b = 0.0f;
        if (i < 36)       b = loc_b[i];
        else if (i < 54)  b = score_b[i - 36];
        g_bias[i] = b;
    }

    // ---- anchors
    if (i < HWP * 9) {
        int hw = i / 9, a = i % 9;
        int hy = hw / WW, wx = hw % WW;
        const double ratios[3] = {0.5, 1.0, 2.0};
        const double scales[3] = {8.0, 16.0, 32.0};
        double r = ratios[a / 3];
        double s = scales[a % 3];
        double ha = 16.0 * s * sqrt(r);
        double wa = 16.0 * s * sqrt(1.0 / r);
        float sy = (float)(hy * 16);
        float sx = (float)(wx * 16);
        float4 v;
        v.x = sy + (float)(8.0 - ha * 0.5);
        v.y = sx + (float)(8.0 - wa * 0.5);
        v.z = sy + (float)(8.0 + ha * 0.5);
        v.w = sx + (float)(8.0 + wa * 0.5);
        reinterpret_cast<float4*>(out_anch)[i] = v;
    }
}

// ---------------------------------------------------------------- main
// CTA = 256 px x 56 outs, 256 threads / 8 warps, warp -> 32 px (2 m-tiles:
// B-fragment L1 traffic amortized over 2x pixels). cp.async 4-stage ring,
// 3 in flight. Epilogue staged through SMEM -> fully coalesced float4 global
// stores (8x fewer store wavefronts than fragment-direct).
__global__ __launch_bounds__(256, 2)
void rpn_hmma_kernel(const float* __restrict__ x, float* __restrict__ out) {
    extern __shared__ __align__(16) float ringf[];

    const int tid  = threadIdx.x;
    const int lane = tid & 31;
    const int wid  = tid >> 5;
    const int b    = blockIdx.x;
    const int n    = b / TILES_PER_IMG;
    const int px0  = (b % TILES_PER_IMG) * PX_TILE;

    const float* xn = x + (size_t)n * CC * HWP + px0;

    // producer: thread copies row (tid>>4), 64B at (tid&15)*64
    const int prow = tid >> 4;          // 0..15 (channel within ktile)
    const int pcol = (tid & 15) * 16;   // float offset within row
    const uint32_t ring_u = smem_u32(ringf);
    const uint32_t pdst   = ring_u + (uint32_t)(prow * ROWW + pcol) * 4;
    const float*   psrc   = xn + (size_t)prow * HWP + pcol;

    // consumer: lane reads ch = 2*(lane&3)+{0,1,8,9},
    //           px = wid*32 + (lane>>2) + {0,8} (mt0), +16 (mt1)
    const float* cbase = ringf + (2 * (lane & 3)) * ROWW + wid * 32 + (lane >> 2);

    float acc[2][NTILES][4];
    #pragma unroll
    for (int mt = 0; mt < 2; mt++)
        #pragma unroll
        for (int nt = 0; nt < NTILES; nt++)
            #pragma unroll
            for (int q = 0; q < 4; q++) acc[mt][nt][q] = 0.0f;

    // prologue: stages 0..2
    ISSUE_P(psrc,                    pdst);
    ISSUE_P(psrc + (size_t)16 * HWP, pdst + STAGE_BYTES);
    ISSUE_P(psrc + (size_t)32 * HWP, pdst + 2 * STAGE_BYTES);

    const uint4* bp = reinterpret_cast<const uint4*>(g_bfrag + (size_t)lane * 16);
    const float* wsrc = psrc + (size_t)48 * HWP;   // stage kt+3 source
    uint32_t soff_w = 3 * STAGE_BYTES;             // slot (kt+3)%4
    int soff_c = 0;                                // slot kt%4

    for (int kt = 0; kt < NKT; kt++) {
        // outstanding groups kt..kt+2 -> wait_group 2 drains stage kt
        asm volatile("cp.async.wait_group 2;" ::: "memory");
        __syncthreads();

        // issue stage kt+3 into slot of kt-1 (reads retired at barrier)
        if (kt + 3 < NKT) {
            ISSUE_P(wsrc, pdst + soff_w);
            wsrc += (size_t)16 * HWP;
            soff_w += STAGE_BYTES;
            if (soff_w == STAGES * STAGE_BYTES) soff_w = 0;
        } else {
            asm volatile("cp.async.commit_group;" ::: "memory");
        }

        // consume stage kt: two m-tiles share the B fragments
        const float* c = cbase + soff_c;
        uint32_t a0[4], a1[4];
        {
            float f0 = c[0],        f1 = c[8];
            float f2 = c[ROWW],     f3 = c[ROWW + 8];
            float f4 = c[8 * ROWW], f5 = c[8 * ROWW + 8];
            float f6 = c[9 * ROWW], f7 = c[9 * ROWW + 8];
            CVT2(a0[0], f0, f2);
            CVT2(a0[1], f1, f3);
            CVT2(a0[2], f4, f6);
            CVT2(a0[3], f5, f7);
        }
        {
            const float* c1 = c + 16;
            float f0 = c1[0],        f1 = c1[8];
            float f2 = c1[ROWW],     f3 = c1[ROWW + 8];
            float f4 = c1[8 * ROWW], f5 = c1[8 * ROWW + 8];
            float f6 = c1[9 * ROWW], f7 = c1[9 * ROWW + 8];
            CVT2(a1[0], f0, f2);
            CVT2(a1[1], f1, f3);
            CVT2(a1[2], f4, f6);
            CVT2(a1[3], f5, f7);
        }

        uint4 q0 = bp[0], q1 = bp[1], q2 = bp[2], q3 = bp[3];
        MMA16816(acc[0][0], a0, q0.x, q0.y);
        MMA16816(acc[1][0], a1, q0.x, q0.y);
        MMA16816(acc[0][1], a0, q0.z, q0.w);
        MMA16816(acc[1][1], a1, q0.z, q0.w);
        MMA16816(acc[0][2], a0, q1.x, q1.y);
        MMA16816(acc[1][2], a1, q1.x, q1.y);
        MMA16816(acc[0][3], a0, q1.z, q1.w);
        MMA16816(acc[1][3], a1, q1.z, q1.w);
        MMA16816(acc[0][4], a0, q2.x, q2.y);
        MMA16816(acc[1][4], a1, q2.x, q2.y);
        MMA16816(acc[0][5], a0, q2.z, q2.w);
        MMA16816(acc[1][5], a1, q2.z, q2.w);
        MMA16816(acc[0][6], a0, q3.x, q3.y);
        MMA16816(acc[1][6], a1, q3.x, q3.y);

        bp += 128;   // next ktile block: 32 lanes x 16 u32 = 128 uint4
        soff_c += STAGE_FLOATS;
        if (soff_c == STAGES * STAGE_FLOATS) soff_c = 0;
    }

    // ---- epilogue: stage fragments into SMEM, then coalesced global stores
    asm volatile("cp.async.wait_group 0;" ::: "memory");
    __syncthreads();   // ring fully drained; reuse as staging

    const int l4 = lane >> 2;
    const int l2 = (lane & 3) * 2;
    #pragma unroll
    for (int mt = 0; mt < 2; mt++) {
        #pragma unroll
        for (int h = 0; h < 2; h++) {
            int pix = wid * 32 + mt * 16 + h * 8 + l4;   // 0..255
            #pragma unroll
            for (int nt = 0; nt < NTILES; nt++) {
                int col = nt * 8 + l2;
                float v0 = acc[mt][nt][2 * h]     + g_bias[col];
                float v1 = acc[mt][nt][2 * h + 1] + g_bias[col + 1];
                if (col < 36) {
                    ringf[EPI_LOC + pix * 36 + col]     = v0;
                    ringf[EPI_LOC + pix * 36 + col + 1] = v1;
                } else if (col < 54) {
                    ringf[EPI_SC + pix * 18 + (col - 36)]     = v0;
                    ringf[EPI_SC + pix * 18 + (col - 36) + 1] = v1;
                    ringf[EPI_FG + pix * 9 + ((col - 36) >> 1)] =
                        1.0f / (1.0f + __expf(v0 - v1));
                }
            }
        }
    }
    __syncthreads();

    // coalesced copies: contiguous runs since CTA covers 256 consecutive px
    const size_t gpix0 = (size_t)n * HWP + px0;
    {
        float4* dst = reinterpret_cast<float4*>(out + gpix0 * 36);
        const float4* src = reinterpret_cast<const float4*>(ringf + EPI_LOC);
        #pragma unroll
        for (int i = 0; i < 9; i++) dst[tid + i * 256] = src[tid + i * 256];
    }
    {
        float4* dst = reinterpret_cast<float4*>(out + SC_BASE + gpix0 * 18);
        const float4* src = reinterpret_cast<const float4*>(ringf + EPI_SC);
        #pragma unroll
        for (int i = 0; i < 4; i++) dst[tid + i * 256] = src[tid + i * 256];
        if (tid < 128) dst[tid + 4 * 256] = src[tid + 4 * 256];
    }
    {
        // fg block: 256*9 floats = 576 float4 -> needs 3 passes of 256
        float4* dst = reinterpret_cast<float4*>(out + FG_BASE + gpix0 * 9);
        const float4* src = reinterpret_cast<const float4*>(ringf + EPI_FG);
        #pragma unroll
        for (int i = 0; i < 3; i++) {
            int idx = tid + i * 256;
            if (idx < 576) dst[idx] = src[idx];
        }
    }
}

// ---------------------------------------------------------------- launch
extern "C" void kernel_launch(void* const* d_in, const int* in_sizes, int n_in,
                              void* d_out, int out_size) {
    (void)in_sizes; (void)n_in; (void)out_size;
    const float* x       = (const float*)d_in[0];
    const float* loc_w   = (const float*)d_in[1];
    const float* loc_b   = (const float*)d_in[2];
    const float* score_w = (const float*)d_in[3];
    const float* score_b = (const float*)d_in[4];
    float* out = (float*)d_out;

    // opt-in to dynamic smem sizing (host attribute, capture-safe)
    static int smem_set = 0;
    if (!smem_set) {
        cudaFuncSetAttribute(rpn_hmma_kernel,
                             cudaFuncAttributeMaxDynamicSharedMemorySize,
                             SMEM_TOTAL);
        smem_set = 1;
    }

    pack_w_kernel<<<(HWP * 9 + 255) / 256, 256>>>(
        loc_w, loc_b, score_w, score_b, out + ANCH_BASE);

    rpn_hmma_kernel<<<NB * TILES_PER_IMG, 256, SMEM_TOTAL>>>(x, out);
}

// round 16
// speedup vs baseline: 1.7193x; 1.3344x over previous
#include <cuda_runtime.h>
#include <cuda_fp16.h>
#include <math.h>
#include <stdint.h>

// ---------------------------------------------------------------- constants
#define NB     16
#define CC     512
#define HWP    6144            // 64*96
#define WW     96
#define PX_TILE 128            // pixels per CTA
#define TILES_PER_IMG 48       // 6144/128
#define NKT    32              // 32 k-tiles of 16 = K 512
#define NTILES 7               // 7 n-tiles of 8 = 56 cols (54 real)

// epilogue staging offsets (floats): 128*36 | 128*18 | 128*9 = 8064 total
#define EPI_LOC   0
#define EPI_SC    4608
#define EPI_FG    6912
#define EPI_TOT   8064

// Output layout (floats): [rpn_loc | rpn_score | rpn_fg | anchor]
#define SC_BASE   3538944
#define FG_BASE   5308416
#define ANCH_BASE 6193152

// B fragments (fp16): [ktile(32)][lane(32)][16 u32 (7 ntiles*2 + pad)]
__device__ uint32_t g_bfrag[NKT * 32 * 16];   // 64 KB
__device__ float g_bias[64];

// ---------------------------------------------------------------- helpers
#define MMA16816(c, a, b0, b1)                                                \
    asm volatile("mma.sync.aligned.m16n8k16.row.col.f32.f16.f16.f32 "         \
        "{%0,%1,%2,%3}, {%4,%5,%6,%7}, {%8,%9}, {%0,%1,%2,%3};"               \
        : "+f"((c)[0]), "+f"((c)[1]), "+f"((c)[2]), "+f"((c)[3])              \
        : "r"((a)[0]), "r"((a)[1]), "r"((a)[2]), "r"((a)[3]),                 \
          "r"(b0), "r"(b1))

#define CVT2(d, flo, fhi)                                                     \
    asm("cvt.rn.f16x2.f32 %0, %1, %2;" : "=r"(d) : "f"(fhi), "f"(flo))

// ---------------------------------------------------------------- helper kernel
// Fused: B-fragment bake (fp16) + bias + anchors. 2 launches/call total.
__global__ void pack_w_kernel(const float* __restrict__ loc_w,
                              const float* __restrict__ loc_b,
                              const float* __restrict__ score_w,
                              const float* __restrict__ score_b,
                              float* __restrict__ out_anch) {
    int i = blockIdx.x * blockDim.x + threadIdx.x;

    // ---- B fragments: 32*32*8 = 8192 slots
    if (i < 8192) {
        int kt   = i >> 8;           // ktile 0..31
        int lane = (i >> 3) & 31;
        int nts  = i & 7;            // ntile slot (7 = zero pad)
        int o    = nts * 8 + (lane >> 2);
        int k0   = kt * 16 + 2 * (lane & 3);

        float w[4];
        #pragma unroll
        for (int q = 0; q < 4; q++) {
            int c = k0 + (q & 1) + (q >> 1) * 8;
            float v = 0.0f;
            if (o < 36)       v = loc_w[o * CC + c];
            else if (o < 54)  v = score_w[(o - 36) * CC + c];
            w[q] = v;
        }
        unsigned short u[4];
        #pragma unroll
        for (int q = 0; q < 4; q++)
            u[q] = __half_as_ushort(__float2half_rn(w[q]));
        int frag = kt * 32 + lane;
        g_bfrag[frag * 16 + nts * 2]     = (uint32_t)u[0] | ((uint32_t)u[1] << 16);
        g_bfrag[frag * 16 + nts * 2 + 1] = (uint32_t)u[2] | ((uint32_t)u[3] << 16);
    }

    // ---- bias
    if (i < 64) {
        float b = 0.0f;
        if (i < 36)       b = loc_b[i];
        else if (i < 54)  b = score_b[i - 36];
        g_bias[i] = b;
    }

    // ---- anchors
    if (i < HWP * 9) {
        int hw = i / 9, a = i % 9;
        int hy = hw / WW, wx = hw % WW;
        const double ratios[3] = {0.5, 1.0, 2.0};
        const double scales[3] = {8.0, 16.0, 32.0};
        double r = ratios[a / 3];
        double s = scales[a % 3];
        double ha = 16.0 * s * sqrt(r);
        double wa = 16.0 * s * sqrt(1.0 / r);
        float sy = (float)(hy * 16);
        float sx = (float)(wx * 16);
        float4 v;
        v.x = sy + (float)(8.0 - ha * 0.5);
        v.y = sx + (float)(8.0 - wa * 0.5);
        v.z = sy + (float)(8.0 + ha * 0.5);
        v.w = sx + (float)(8.0 + wa * 0.5);
        reinterpret_cast<float4*>(out_anch)[i] = v;
    }
}

// ---------------------------------------------------------------- main
// R7 mainloop verbatim (best measured: direct global A loads, no staging,
// no barriers, 1-ktile register prefetch) + R15-validated SMEM-staged
// coalesced epilogue (replaces the scattered float2 stores).
__global__ __launch_bounds__(128, 4)
void rpn_hmma_kernel(const float* __restrict__ x, float* __restrict__ out) {
    __shared__ __align__(16) float epi[EPI_TOT];   // 32,256 B

    const int tid  = threadIdx.x;
    const int lane = tid & 31;
    const int wid  = tid >> 5;
    const int b    = blockIdx.x;
    const int n    = b / TILES_PER_IMG;
    const int px0  = (b % TILES_PER_IMG) * PX_TILE;

    float acc[2][NTILES][4];
    #pragma unroll
    for (int mt = 0; mt < 2; mt++)
        #pragma unroll
        for (int nt = 0; nt < NTILES; nt++)
            #pragma unroll
            for (int q = 0; q < 4; q++) acc[mt][nt][q] = 0.0f;

    // base: this lane's pixel row (fragment row l>>2), this lane's channel pair
    const float* xw = x + (size_t)n * CC * HWP + px0 + wid * 32 + (lane >> 2);
    const int csub = (lane & 3) * 2;

    // f[buf][dci*4 + dpi]: dci -> dc {0,1,8,9}, dpi -> dpx {0,8,16,24}
    float f[2][16];

    // preload ktile 0
    {
        const float* p = xw + (size_t)csub * HWP;
        #pragma unroll
        for (int dci = 0; dci < 4; dci++) {
            int dc = (dci & 1) + (dci >> 1) * 8;
            #pragma unroll
            for (int dpi = 0; dpi < 4; dpi++)
                f[0][dci * 4 + dpi] = p[(size_t)dc * HWP + dpi * 8];
        }
    }

    #pragma unroll 2
    for (int kt = 0; kt < NKT; kt++) {
        const int cur = kt & 1, nxt = cur ^ 1;

        // prefetch next ktile (16 independent LDG.32, front-batched)
        if (kt < NKT - 1) {
            const float* p = xw + (size_t)((kt + 1) * 16 + csub) * HWP;
            #pragma unroll
            for (int dci = 0; dci < 4; dci++) {
                int dc = (dci & 1) + (dci >> 1) * 8;
                #pragma unroll
                for (int dpi = 0; dpi < 4; dpi++)
                    f[nxt][dci * 4 + dpi] = p[(size_t)dc * HWP + dpi * 8];
            }
        }

        // convert current ktile to A fragments
        uint32_t a[2][4];
        #pragma unroll
        for (int mt = 0; mt < 2; mt++) {
            CVT2(a[mt][0], f[cur][0 * 4 + mt * 2],     f[cur][1 * 4 + mt * 2]);
            CVT2(a[mt][1], f[cur][0 * 4 + mt * 2 + 1], f[cur][1 * 4 + mt * 2 + 1]);
            CVT2(a[mt][2], f[cur][2 * 4 + mt * 2],     f[cur][3 * 4 + mt * 2]);
            CVT2(a[mt][3], f[cur][2 * 4 + mt * 2 + 1], f[cur][3 * 4 + mt * 2 + 1]);
        }

        // B fragments from global (L1-resident; identical across CTAs)
        const uint4* bp = reinterpret_cast<const uint4*>(
            g_bfrag + (size_t)(kt * 32 + lane) * 16);
        uint4 q0 = bp[0], q1 = bp[1];
        MMA16816(acc[0][0], a[0], q0.x, q0.y);
        MMA16816(acc[1][0], a[1], q0.x, q0.y);
        MMA16816(acc[0][1], a[0], q0.z, q0.w);
        MMA16816(acc[1][1], a[1], q0.z, q0.w);
        MMA16816(acc[0][2], a[0], q1.x, q1.y);
        MMA16816(acc[1][2], a[1], q1.x, q1.y);
        MMA16816(acc[0][3], a[0], q1.z, q1.w);
        MMA16816(acc[1][3], a[1], q1.z, q1.w);
        uint4 q2 = bp[2], q3 = bp[3];
        MMA16816(acc[0][4], a[0], q2.x, q2.y);
        MMA16816(acc[1][4], a[1], q2.x, q2.y);
        MMA16816(acc[0][5], a[0], q2.z, q2.w);
        MMA16816(acc[1][5], a[1], q2.z, q2.w);
        MMA16816(acc[0][6], a[0], q3.x, q3.y);
        MMA16816(acc[1][6], a[1], q3.x, q3.y);
    }

    // ---- epilogue: stage fragments into SMEM, then coalesced global stores
    const int l4 = lane >> 2;
    const int l2 = (lane & 3) * 2;
    #pragma unroll
    for (int mt = 0; mt < 2; mt++) {
        #pragma unroll
        for (int h = 0; h < 2; h++) {
            int pix = wid * 32 + mt * 16 + h * 8 + l4;   // 0..127
            #pragma unroll
            for (int nt = 0; nt < NTILES; nt++) {
                int col = nt * 8 + l2;
                float v0 = acc[mt][nt][2 * h]     + g_bias[col];
                float v1 = acc[mt][nt][2 * h + 1] + g_bias[col + 1];
                if (col < 36) {
                    epi[EPI_LOC + pix * 36 + col]     = v0;
                    epi[EPI_LOC + pix * 36 + col + 1] = v1;
                } else if (col < 54) {
                    epi[EPI_SC + pix * 18 + (col - 36)]     = v0;
                    epi[EPI_SC + pix * 18 + (col - 36) + 1] = v1;
                    epi[EPI_FG + pix * 9 + ((col - 36) >> 1)] =
                        1.0f / (1.0f + __expf(v0 - v1));
                }
            }
        }
    }
    __syncthreads();

    // coalesced copies: contiguous runs since CTA covers 128 consecutive px
    const size_t gpix0 = (size_t)n * HWP + px0;
    {
        // loc: 128*36 = 4608 floats = 1152 float4
        float4* dst = reinterpret_cast<float4*>(out + gpix0 * 36);
        const float4* src = reinterpret_cast<const float4*>(epi + EPI_LOC);
        #pragma unroll
        for (int i = 0; i < 9; i++) dst[tid + i * 128] = src[tid + i * 128];
    }
    {
        // score: 128*18 = 2304 floats = 576 float4
        float4* dst = reinterpret_cast<float4*>(out + SC_BASE + gpix0 * 18);
        const float4* src = reinterpret_cast<const float4*>(epi + EPI_SC);
        #pragma unroll
        for (int i = 0; i < 4; i++) dst[tid + i * 128] = src[tid + i * 128];
        if (tid < 64) dst[tid + 4 * 128] = src[tid + 4 * 128];
    }
    {
        // fg: 128*9 = 1152 floats = 288 float4
        float4* dst = reinterpret_cast<float4*>(out + FG_BASE + gpix0 * 9);
        const float4* src = reinterpret_cast<const float4*>(epi + EPI_FG);
        #pragma unroll
        for (int i = 0; i < 3; i++) {
            int idx = tid + i * 128;
            if (idx < 288) dst[idx] = src[idx];
        }
    }
}

// ---------------------------------------------------------------- launch
extern "C" void kernel_launch(void* const* d_in, const int* in_sizes, int n_in,
                              void* d_out, int out_size) {
    (void)in_sizes; (void)n_in; (void)out_size;
    const float* x       = (const float*)d_in[0];
    const float* loc_w   = (const float*)d_in[1];
    const float* loc_b   = (const float*)d_in[2];
    const float* score_w = (const float*)d_in[3];
    const float* score_b = (const float*)d_in[4];
    float* out = (float*)d_out;

    pack_w_kernel<<<(HWP * 9 + 255) / 256, 256>>>(
        loc_w, loc_b, score_w, score_b, out + ANCH_BASE);

    rpn_hmma_kernel<<<NB * TILES_PER_IMG, 128>>>(x, out);
}

// round 17
// speedup vs baseline: 1.7565x; 1.0217x over previous
#include <cuda_runtime.h>
#include <cuda_fp16.h>
#include <math.h>
#include <stdint.h>

// ---------------------------------------------------------------- constants
#define NB     16
#define CC     512
#define HWP    6144            // 64*96
#define WW     96
#define PX_TILE 128            // pixels per CTA
#define TILES_PER_IMG 48       // 6144/128
#define NKT    32              // 32 k-tiles of 16 = K 512
#define NTILES 7               // 7 n-tiles of 8 = 56 cols (54 real)

// epilogue staging offsets (floats): 128*36 | 128*18 | 128*9 = 8064 total
#define EPI_LOC   0
#define EPI_SC    4608
#define EPI_FG    6912
#define EPI_TOT   8064

// Output layout (floats): [rpn_loc | rpn_score | rpn_fg | anchor]
#define SC_BASE   3538944
#define FG_BASE   5308416
#define ANCH_BASE 6193152

// B fragments (fp16): [ktile(32)][lane(32)][16 u32 (7 ntiles*2 + pad)]
__device__ uint32_t g_bfrag[NKT * 32 * 16];   // 64 KB
__device__ float g_bias[64];

// ---------------------------------------------------------------- helpers
#define MMA16816(c, a, b0, b1)                                                \
    asm volatile("mma.sync.aligned.m16n8k16.row.col.f32.f16.f16.f32 "         \
        "{%0,%1,%2,%3}, {%4,%5,%6,%7}, {%8,%9}, {%0,%1,%2,%3};"               \
        : "+f"((c)[0]), "+f"((c)[1]), "+f"((c)[2]), "+f"((c)[3])              \
        : "r"((a)[0]), "r"((a)[1]), "r"((a)[2]), "r"((a)[3]),                 \
          "r"(b0), "r"(b1))

#define CVT2(d, flo, fhi)                                                     \
    asm("cvt.rn.f16x2.f32 %0, %1, %2;" : "=r"(d) : "f"(fhi), "f"(flo))

// ---------------------------------------------------------------- helper kernel
// Fused: B-fragment bake (fp16) + bias + anchors. 2 launches/call total.
__global__ void pack_w_kernel(const float* __restrict__ loc_w,
                              const float* __restrict__ loc_b,
                              const float* __restrict__ score_w,
                              const float* __restrict__ score_b,
                              float* __restrict__ out_anch) {
    int i = blockIdx.x * blockDim.x + threadIdx.x;

    // ---- B fragments: 32*32*8 = 8192 slots
    if (i < 8192) {
        int kt   = i >> 8;           // ktile 0..31
        int lane = (i >> 3) & 31;
        int nts  = i & 7;            // ntile slot (7 = zero pad)
        int o    = nts * 8 + (lane >> 2);
        int k0   = kt * 16 + 2 * (lane & 3);

        float w[4];
        #pragma unroll
        for (int q = 0; q < 4; q++) {
            int c = k0 + (q & 1) + (q >> 1) * 8;
            float v = 0.0f;
            if (o < 36)       v = loc_w[o * CC + c];
            else if (o < 54)  v = score_w[(o - 36) * CC + c];
            w[q] = v;
        }
        unsigned short u[4];
        #pragma unroll
        for (int q = 0; q < 4; q++)
            u[q] = __half_as_ushort(__float2half_rn(w[q]));
        int frag = kt * 32 + lane;
        g_bfrag[frag * 16 + nts * 2]     = (uint32_t)u[0] | ((uint32_t)u[1] << 16);
        g_bfrag[frag * 16 + nts * 2 + 1] = (uint32_t)u[2] | ((uint32_t)u[3] << 16);
    }

    // ---- bias
    if (i < 64) {
        float b = 0.0f;
        if (i < 36)       b = loc_b[i];
        else if (i < 54)  b = score_b[i - 36];
        g_bias[i] = b;
    }

    // ---- anchors (sqrt values hardcoded as exact doubles: bit-identical
    // to np.sqrt(0.5)/np.sqrt(2.0); avoids double-sqrt MUFU chains)
    if (i < HWP * 9) {
        int hw = i / 9, a = i % 9;
        int hy = hw / WW, wx = hw % WW;
        const double sr_h[3] = {0.7071067811865476, 1.0, 1.4142135623730951};
        const double sr_w[3] = {1.4142135623730951, 1.0, 0.7071067811865476};
        const double scales[3] = {8.0, 16.0, 32.0};
        int ri = a / 3;
        double s = scales[a % 3];
        double ha = 16.0 * s * sr_h[ri];
        double wa = 16.0 * s * sr_w[ri];
        float sy = (float)(hy * 16);
        float sx = (float)(wx * 16);
        float4 v;
        v.x = sy + (float)(8.0 - ha * 0.5);
        v.y = sx + (float)(8.0 - wa * 0.5);
        v.z = sy + (float)(8.0 + ha * 0.5);
        v.w = sx + (float)(8.0 + wa * 0.5);
        reinterpret_cast<float4*>(out_anch)[i] = v;
    }
}

// ---------------------------------------------------------------- main
// R16 structure, A loads vectorized: lane l loads float4 px 4*(l>>2)+{0..3}
// at ch 2*(l&3)+dc -> each row access is a full 128B line (4 LDG.128/ktile,
// 16 wavefronts per 2KB vs 64 before). The 4 px map to (mt,h)=(q&1,q>>1);
// pixel permutation absorbed by the SMEM-staged epilogue's pix formula.
__global__ __launch_bounds__(128, 4)
void rpn_hmma_kernel(const float* __restrict__ x, float* __restrict__ out) {
    __shared__ __align__(16) float epi[EPI_TOT];   // 32,256 B

    const int tid  = threadIdx.x;
    const int lane = tid & 31;
    const int wid  = tid >> 5;
    const int b    = blockIdx.x;
    const int n    = b / TILES_PER_IMG;
    const int px0  = (b % TILES_PER_IMG) * PX_TILE;

    float acc[2][NTILES][4];
    #pragma unroll
    for (int mt = 0; mt < 2; mt++)
        #pragma unroll
        for (int nt = 0; nt < NTILES; nt++)
            #pragma unroll
            for (int q = 0; q < 4; q++) acc[mt][nt][q] = 0.0f;

    // base: px quad 4*(l>>2), channel pair base 2*(l&3)
    const float* xw = x + (size_t)n * CC * HWP + px0 + wid * 32 + 4 * (lane >> 2);
    const int csub = (lane & 3) * 2;

    // f[buf][dci]: dci -> dc {0,1,8,9}; float4 = px quad (mt,h)=(q&1,q>>1)
    float4 f[2][4];

    // preload ktile 0
    #pragma unroll
    for (int dci = 0; dci < 4; dci++) {
        int dc = (dci & 1) + (dci >> 1) * 8;
        f[0][dci] = *reinterpret_cast<const float4*>(
            xw + (size_t)(csub + dc) * HWP);
    }

    #pragma unroll 2
    for (int kt = 0; kt < NKT; kt++) {
        const int cur = kt & 1, nxt = cur ^ 1;

        // prefetch next ktile (4 independent LDG.128, full-line rows)
        if (kt < NKT - 1) {
            #pragma unroll
            for (int dci = 0; dci < 4; dci++) {
                int dc = (dci & 1) + (dci >> 1) * 8;
                f[nxt][dci] = *reinterpret_cast<const float4*>(
                    xw + (size_t)((kt + 1) * 16 + csub + dc) * HWP);
            }
        }

        // convert current ktile to A fragments
        // a[mt][0]: row r   k(csub,+1) = comp mt   of dc0,dc1
        // a[mt][1]: row r+8 same k     = comp mt+2
        // a[mt][2]: row r   k+8        = comp mt   of dc8,dc9
        // a[mt][3]: row r+8 k+8        = comp mt+2
        uint32_t a[2][4];
        {
            const float* f0 = &f[cur][0].x;
            const float* f1 = &f[cur][1].x;
            const float* f2 = &f[cur][2].x;
            const float* f3 = &f[cur][3].x;
            #pragma unroll
            for (int mt = 0; mt < 2; mt++) {
                CVT2(a[mt][0], f0[mt],     f1[mt]);
                CVT2(a[mt][1], f0[mt + 2], f1[mt + 2]);
                CVT2(a[mt][2], f2[mt],     f3[mt]);
                CVT2(a[mt][3], f2[mt + 2], f3[mt + 2]);
            }
        }

        // B fragments from global (L1-resident; identical across CTAs)
        const uint4* bp = reinterpret_cast<const uint4*>(
            g_bfrag + (size_t)(kt * 32 + lane) * 16);
        uint4 q0 = bp[0], q1 = bp[1];
        MMA16816(acc[0][0], a[0], q0.x, q0.y);
        MMA16816(acc[1][0], a[1], q0.x, q0.y);
        MMA16816(acc[0][1], a[0], q0.z, q0.w);
        MMA16816(acc[1][1], a[1], q0.z, q0.w);
        MMA16816(acc[0][2], a[0], q1.x, q1.y);
        MMA16816(acc[1][2], a[1], q1.x, q1.y);
        MMA16816(acc[0][3], a[0], q1.z, q1.w);
        MMA16816(acc[1][3], a[1], q1.z, q1.w);
        uint4 q2 = bp[2], q3 = bp[3];
        MMA16816(acc[0][4], a[0], q2.x, q2.y);
        MMA16816(acc[1][4], a[1], q2.x, q2.y);
        MMA16816(acc[0][5], a[0], q2.z, q2.w);
        MMA16816(acc[1][5], a[1], q2.z, q2.w);
        MMA16816(acc[0][6], a[0], q3.x, q3.y);
        MMA16816(acc[1][6], a[1], q3.x, q3.y);
    }

    // ---- epilogue: stage fragments into SMEM, then coalesced global stores
    const int l4 = lane >> 2;
    const int l2 = (lane & 3) * 2;
    #pragma unroll
    for (int mt = 0; mt < 2; mt++) {
        #pragma unroll
        for (int h = 0; h < 2; h++) {
            // px permutation from the float4 A loads:
            int pix = wid * 32 + 4 * l4 + 2 * h + mt;    // 0..127
            #pragma unroll
            for (int nt = 0; nt < NTILES; nt++) {
                int col = nt * 8 + l2;
                float v0 = acc[mt][nt][2 * h]     + g_bias[col];
                float v1 = acc[mt][nt][2 * h + 1] + g_bias[col + 1];
                if (col < 36) {
                    epi[EPI_LOC + pix * 36 + col]     = v0;
                    epi[EPI_LOC + pix * 36 + col + 1] = v1;
                } else if (col < 54) {
                    epi[EPI_SC + pix * 18 + (col - 36)]     = v0;
                    epi[EPI_SC + pix * 18 + (col - 36) + 1] = v1;
                    epi[EPI_FG + pix * 9 + ((col - 36) >> 1)] =
                        1.0f / (1.0f + __expf(v0 - v1));
                }
            }
        }
    }
    __syncthreads();

    // coalesced copies: contiguous runs since CTA covers 128 consecutive px
    const size_t gpix0 = (size_t)n * HWP + px0;
    {
        // loc: 128*36 = 4608 floats = 1152 float4
        float4* dst = reinterpret_cast<float4*>(out + gpix0 * 36);
        const float4* src = reinterpret_cast<const float4*>(epi + EPI_LOC);
        #pragma unroll
        for (int i = 0; i < 9; i++) dst[tid + i * 128] = src[tid + i * 128];
    }
    {
        // score: 128*18 = 2304 floats = 576 float4
        float4* dst = reinterpret_cast<float4*>(out + SC_BASE + gpix0 * 18);
        const float4* src = reinterpret_cast<const float4*>(epi + EPI_SC);
        #pragma unroll
        for (int i = 0; i < 4; i++) dst[tid + i * 128] = src[tid + i * 128];
        if (tid < 64) dst[tid + 4 * 128] = src[tid + 4 * 128];
    }
    {
        // fg: 128*9 = 1152 floats = 288 float4
        float4* dst = reinterpret_cast<float4*>(out + FG_BASE + gpix0 * 9);
        const float4* src = reinterpret_cast<const float4*>(epi + EPI_FG);
        #pragma unroll
        for (int i = 0; i < 3; i++) {
            int idx = tid + i * 128;
            if (idx < 288) dst[idx] = src[idx];
        }
    }
}

// ---------------------------------------------------------------- launch
extern "C" void kernel_launch(void* const* d_in, const int* in_sizes, int n_in,
                              void* d_out, int out_size) {
    (void)in_sizes; (void)n_in; (void)out_size;
    const float* x       = (const float*)d_in[0];
    const float* loc_w   = (const float*)d_in[1];
    const float* loc_b   = (const float*)d_in[2];
    const float* score_w = (const float*)d_in[3];
    const float* score_b = (const float*)d_in[4];
    float* out = (float*)d_out;

    pack_w_kernel<<<(HWP * 9 + 255) / 256, 256>>>(
        loc_w, loc_b, score_w, score_b, out + ANCH_BASE);

    rpn_hmma_kernel<<<NB * TILES_PER_IMG, 128>>>(x, out);
}